// round 12
// baseline (speedup 1.0000x reference)
#include <cuda_runtime.h>
#include <cstdint>

#define NUM_RAYS   262144
#define RAY_LEN    128
#define NUM_LEAVES 1048576
#define LEAF_MASK  (NUM_LEAVES - 1)
#define MAX_DIST   1e10f
#define EPS_F      1e-10f

// Precomputed sigmoid(logits) — 4 MB device scratch.
__device__ float g_opacity[NUM_LEAVES];

// ---------------------------------------------------------------------------
// Bitwise replication of XLA:CPU's fast tanh (Eigen generic_fast_tanh_float):
// plain rn mul/add (no FMA contraction), correctly-rounded division.
// DO NOT TOUCH — 1 ulp here is ~7e-4 relative in sigmoid(-10); this is what
// makes rel_err 2.9e-4 instead of 1.7e-3.
// ---------------------------------------------------------------------------
__device__ __forceinline__ float xla_fast_tanh(float x) {
    if (fabsf(x) < 0.0004f) return x;
    float xc = fminf(fmaxf(x, -7.90531110763549805f), 7.90531110763549805f);
    float x2 = __fmul_rn(xc, xc);
    float p = -2.76076847742355e-16f;
    p = __fadd_rn(__fmul_rn(p, x2),  2.00018790482477e-13f);
    p = __fadd_rn(__fmul_rn(p, x2), -8.60467152213735e-11f);
    p = __fadd_rn(__fmul_rn(p, x2),  5.12229709037114e-08f);
    p = __fadd_rn(__fmul_rn(p, x2),  1.48572235717979e-05f);
    p = __fadd_rn(__fmul_rn(p, x2),  6.37261928875436e-04f);
    p = __fadd_rn(__fmul_rn(p, x2),  4.89352455891786e-03f);
    p = __fmul_rn(p, xc);
    float q =  1.19825839466702e-06f;
    q = __fadd_rn(__fmul_rn(q, x2),  1.18534705686654e-04f);
    q = __fadd_rn(__fmul_rn(q, x2),  2.26843463243900e-03f);
    q = __fadd_rn(__fmul_rn(q, x2),  4.89352518554385e-03f);
    return __fdiv_rn(p, q);
}

__global__ void sigmoid_prepass(const float4* __restrict__ logits4, int n4) {
    int i = blockIdx.x * blockDim.x + threadIdx.x;
    if (i < n4) {
        // __ldcs: evict-first — don't let the 4 MB logits stream displace the
        // opacity table (the only L2-resident data the main kernel reuses).
        float4 x = __ldcs(&logits4[i]);
        float4 r;
        r.x = __fadd_rn(0.5f, __fmul_rn(0.5f, xla_fast_tanh(__fmul_rn(0.5f, x.x))));
        r.y = __fadd_rn(0.5f, __fmul_rn(0.5f, xla_fast_tanh(__fmul_rn(0.5f, x.y))));
        r.z = __fadd_rn(0.5f, __fmul_rn(0.5f, xla_fast_tanh(__fmul_rn(0.5f, x.z))));
        r.w = __fadd_rn(0.5f, __fmul_rn(0.5f, xla_fast_tanh(__fmul_rn(0.5f, x.w))));
        *reinterpret_cast<float4*>(&g_opacity[i * 4]) = r;
    }
    // PDL: table stores for this thread are done — allow dependents to launch.
    cudaTriggerProgrammaticLaunchCompletion();
}

// Near-correctly-rounded exp(-x) for x in [0, 0.0625]; expf fallback above.
// DO NOT TOUCH — load-bearing for the cancellation-amplified 1-exp(-x).
__device__ __forceinline__ float exp_neg_cr(float x) {   // x >= 0
    if (x > 0.0625f) return expf(-x);
    float hi = __fadd_rn(1.0f, -x);
    float t  = __fadd_rn(1.0f, -hi);
    float lo = __fadd_rn(t, -x);
    float c = x * x * fmaf(x, fmaf(x, fmaf(x, -8.3333333e-3f, 4.1666668e-2f),
                                   -0.16666667f), 0.5f);
    return __fadd_rn(hi, __fadd_rn(lo, c));
}

__device__ __forceinline__ void sample_terms(float o, float d,
                                             float& alpha, float& trans) {
    float x = __fmul_rn(o, d);
    float e = exp_neg_cr(x);
    alpha = __fadd_rn(1.0f, -e);
    trans = fminf(1.0f, __fadd_rn(__fadd_rn(1.0f, -alpha), EPS_F));
}

// Per-ray tail: deltas -> terms -> warp scan -> warp reduce -> out.
__device__ __forceinline__ void process_ray(int lane, int ray,
                                            const float4& ts,
                                            float o0, float o1, float o2, float o3,
                                            float* __restrict__ out)
{
    const float t_next = __shfl_down_sync(0xFFFFFFFFu, ts.x, 1);
    const float d0 = __fadd_rn(ts.y, -ts.x);
    const float d1 = __fadd_rn(ts.z, -ts.y);
    const float d2 = __fadd_rn(ts.w, -ts.z);
    const float d3 = (lane == 31) ? MAX_DIST : __fadd_rn(t_next, -ts.w);

    float a0, a1, a2, a3, tr0, tr1, tr2, tr3;
    sample_terms(o0, d0, a0, tr0);
    sample_terms(o1, d1, a1, tr1);
    sample_terms(o2, d2, a2, tr2);
    sample_terms(o3, d3, a3, tr3);

    if (lane == 0) tr0 = 1.0f;          // shifted-right leading transmittance 1

    const float p0 = tr0;
    const float p1 = p0 * tr1;
    const float p2 = p1 * tr2;
    const float p3 = p2 * tr3;

    float v = p3;
    #pragma unroll
    for (int off = 1; off < 32; off <<= 1) {
        float n = __shfl_up_sync(0xFFFFFFFFu, v, off);
        if (lane >= off) v *= n;
    }
    float pref = __shfl_up_sync(0xFFFFFFFFu, v, 1);
    if (lane == 0) pref = 1.0f;

    float s = pref * (a0 * p0 + a1 * p1 + a2 * p2 + a3 * p3);

    #pragma unroll
    for (int off = 16; off > 0; off >>= 1)
        s += __shfl_down_sync(0xFFFFFFFFu, s, off);

    if (lane == 0) __stcs(&out[ray], s);   // streaming store: don't pollute L2
}

// Two rays per warp (empirically optimal: occ ~91%, 8-deep gather burst).
// PDL: streaming loads (independent of the opacity table) issue before the
// grid-dependency sync; gathers wait for the prepass to be visible.
__global__ __launch_bounds__(256)
void volume_carver_kernel(const float4* __restrict__ t_stops4,   // [NUM_RAYS*32]
                          const int4*   __restrict__ leaves_i4,  // [NUM_RAYS*32]
                          float*        __restrict__ out)
{
    const int lane = threadIdx.x & 31;
    const int warp = blockIdx.x * 8 + (threadIdx.x >> 5);
    const int rayA = warp * 2;
    const int rayB = rayA + 1;

    // ---- streaming loads (evict-first); do not depend on the table ----------
    const int4   lvA = __ldcs(&leaves_i4[rayA * 32 + lane]);
    const int4   lvB = __ldcs(&leaves_i4[rayB * 32 + lane]);
    const float4 tsA = __ldcs(&t_stops4[rayA * 32 + lane]);
    const float4 tsB = __ldcs(&t_stops4[rayB * 32 + lane]);

    // ---- wait for sigmoid table visibility (PDL) -----------------------------
    cudaGridDependencySynchronize();

    // ---- 8 independent gathers, back-to-back ---------------------------------
    const float oA0 = g_opacity[lvA.x & LEAF_MASK];
    const float oA1 = g_opacity[lvA.y & LEAF_MASK];
    const float oA2 = g_opacity[lvA.z & LEAF_MASK];
    const float oA3 = g_opacity[lvA.w & LEAF_MASK];
    const float oB0 = g_opacity[lvB.x & LEAF_MASK];
    const float oB1 = g_opacity[lvB.y & LEAF_MASK];
    const float oB2 = g_opacity[lvB.z & LEAF_MASK];
    const float oB3 = g_opacity[lvB.w & LEAF_MASK];

    process_ray(lane, rayA, tsA, oA0, oA1, oA2, oA3, out);
    process_ray(lane, rayB, tsB, oB0, oB1, oB2, oB3, out);
}

extern "C" void kernel_launch(void* const* d_in, const int* in_sizes, int n_in,
                              void* d_out, int out_size)
{
    const float* t_stops = (const float*)d_in[0];   // [NUM_RAYS*128] f32
    const int*   leaves  = (const int*)d_in[1];     // [NUM_RAYS*128] int32
    const float* logits  = (const float*)d_in[2];   // [NUM_LEAVES]   f32
    float* out = (float*)d_out;

    const int n4 = in_sizes[2] / 4;
    sigmoid_prepass<<<(n4 + 255) / 256, 256>>>((const float4*)logits, n4);

    // Main kernel with programmatic stream serialization (PDL): its launch and
    // streaming prologue overlap the prepass; gathers are fenced by
    // cudaGridDependencySynchronize() in-kernel.
    cudaLaunchConfig_t cfg = {};
    cfg.gridDim  = dim3(NUM_RAYS / 16, 1, 1);   // 8 warps/block, 2 rays/warp
    cfg.blockDim = dim3(256, 1, 1);
    cfg.dynamicSmemBytes = 0;
    cfg.stream = 0;
    cudaLaunchAttribute attr[1];
    attr[0].id = cudaLaunchAttributeProgrammaticStreamSerialization;
    attr[0].val.programmaticStreamSerializationAllowed = 1;
    cfg.attrs = attr;
    cfg.numAttrs = 1;

    cudaLaunchKernelEx(&cfg, volume_carver_kernel,
                       (const float4*)t_stops, (const int4*)leaves, out);
}

// round 13
// speedup vs baseline: 1.0023x; 1.0023x over previous
#include <cuda_runtime.h>
#include <cstdint>

#define NUM_RAYS   262144
#define RAY_LEN    128
#define NUM_LEAVES 1048576
#define LEAF_MASK  (NUM_LEAVES - 1)
#define MAX_DIST   1e10f
#define EPS_F      1e-10f

// Precomputed sigmoid(logits) — 4 MB device scratch.
__device__ float g_opacity[NUM_LEAVES];

// ---------------------------------------------------------------------------
// Bitwise replication of XLA:CPU's fast tanh (Eigen generic_fast_tanh_float):
// plain rn mul/add (no FMA contraction), correctly-rounded division.
// DO NOT TOUCH — 1 ulp here is ~7e-4 relative in sigmoid(-10); this is what
// makes rel_err 2.9e-4 instead of 1.7e-3.
// ---------------------------------------------------------------------------
__device__ __forceinline__ float xla_fast_tanh(float x) {
    if (fabsf(x) < 0.0004f) return x;
    float xc = fminf(fmaxf(x, -7.90531110763549805f), 7.90531110763549805f);
    float x2 = __fmul_rn(xc, xc);
    float p = -2.76076847742355e-16f;
    p = __fadd_rn(__fmul_rn(p, x2),  2.00018790482477e-13f);
    p = __fadd_rn(__fmul_rn(p, x2), -8.60467152213735e-11f);
    p = __fadd_rn(__fmul_rn(p, x2),  5.12229709037114e-08f);
    p = __fadd_rn(__fmul_rn(p, x2),  1.48572235717979e-05f);
    p = __fadd_rn(__fmul_rn(p, x2),  6.37261928875436e-04f);
    p = __fadd_rn(__fmul_rn(p, x2),  4.89352455891786e-03f);
    p = __fmul_rn(p, xc);
    float q =  1.19825839466702e-06f;
    q = __fadd_rn(__fmul_rn(q, x2),  1.18534705686654e-04f);
    q = __fadd_rn(__fmul_rn(q, x2),  2.26843463243900e-03f);
    q = __fadd_rn(__fmul_rn(q, x2),  4.89352518554385e-03f);
    return __fdiv_rn(p, q);
}

__global__ void sigmoid_prepass(const float4* __restrict__ logits4, int n4) {
    int i = blockIdx.x * blockDim.x + threadIdx.x;
    if (i < n4) {
        float4 x = logits4[i];
        float4 r;
        r.x = __fadd_rn(0.5f, __fmul_rn(0.5f, xla_fast_tanh(__fmul_rn(0.5f, x.x))));
        r.y = __fadd_rn(0.5f, __fmul_rn(0.5f, xla_fast_tanh(__fmul_rn(0.5f, x.y))));
        r.z = __fadd_rn(0.5f, __fmul_rn(0.5f, xla_fast_tanh(__fmul_rn(0.5f, x.z))));
        r.w = __fadd_rn(0.5f, __fmul_rn(0.5f, xla_fast_tanh(__fmul_rn(0.5f, x.w))));
        *reinterpret_cast<float4*>(&g_opacity[i * 4]) = r;
    }
    // PDL: table stores for this thread are done — allow dependents to launch.
    cudaTriggerProgrammaticLaunchCompletion();
}

// Near-correctly-rounded exp(-x) for x in [0, 0.0625]; expf fallback above.
// DO NOT TOUCH — load-bearing for the cancellation-amplified 1-exp(-x).
__device__ __forceinline__ float exp_neg_cr(float x) {   // x >= 0
    if (x > 0.0625f) return expf(-x);
    float hi = __fadd_rn(1.0f, -x);
    float t  = __fadd_rn(1.0f, -hi);
    float lo = __fadd_rn(t, -x);
    float c = x * x * fmaf(x, fmaf(x, fmaf(x, -8.3333333e-3f, 4.1666668e-2f),
                                   -0.16666667f), 0.5f);
    return __fadd_rn(hi, __fadd_rn(lo, c));
}

__device__ __forceinline__ void sample_terms(float o, float d,
                                             float& alpha, float& trans) {
    float x = __fmul_rn(o, d);
    float e = exp_neg_cr(x);
    alpha = __fadd_rn(1.0f, -e);
    trans = fminf(1.0f, __fadd_rn(__fadd_rn(1.0f, -alpha), EPS_F));
}

// Per-ray tail: deltas -> terms -> warp scan -> warp reduce -> out.
__device__ __forceinline__ void process_ray(int lane, int ray,
                                            const float4& ts,
                                            float o0, float o1, float o2, float o3,
                                            float* __restrict__ out)
{
    const float t_next = __shfl_down_sync(0xFFFFFFFFu, ts.x, 1);
    const float d0 = __fadd_rn(ts.y, -ts.x);
    const float d1 = __fadd_rn(ts.z, -ts.y);
    const float d2 = __fadd_rn(ts.w, -ts.z);
    const float d3 = (lane == 31) ? MAX_DIST : __fadd_rn(t_next, -ts.w);

    float a0, a1, a2, a3, tr0, tr1, tr2, tr3;
    sample_terms(o0, d0, a0, tr0);
    sample_terms(o1, d1, a1, tr1);
    sample_terms(o2, d2, a2, tr2);
    sample_terms(o3, d3, a3, tr3);

    if (lane == 0) tr0 = 1.0f;          // shifted-right leading transmittance 1

    const float p0 = tr0;
    const float p1 = p0 * tr1;
    const float p2 = p1 * tr2;
    const float p3 = p2 * tr3;

    float v = p3;
    #pragma unroll
    for (int off = 1; off < 32; off <<= 1) {
        float n = __shfl_up_sync(0xFFFFFFFFu, v, off);
        if (lane >= off) v *= n;
    }
    float pref = __shfl_up_sync(0xFFFFFFFFu, v, 1);
    if (lane == 0) pref = 1.0f;

    float s = pref * (a0 * p0 + a1 * p1 + a2 * p2 + a3 * p3);

    #pragma unroll
    for (int off = 16; off > 0; off >>= 1)
        s += __shfl_down_sync(0xFFFFFFFFu, s, off);

    if (lane == 0) out[ray] = s;
}

// Two rays per warp (empirically optimal: occ ~91%, 8-deep gather burst).
// PDL: streaming loads (independent of the opacity table) issue before the
// grid-dependency sync; gathers wait for the prepass to be visible.
__global__ __launch_bounds__(256)
void volume_carver_kernel(const float4* __restrict__ t_stops4,   // [NUM_RAYS*32]
                          const int4*   __restrict__ leaves_i4,  // [NUM_RAYS*32]
                          float*        __restrict__ out)
{
    const int lane = threadIdx.x & 31;
    const int warp = blockIdx.x * 8 + (threadIdx.x >> 5);
    const int rayA = warp * 2;
    const int rayB = rayA + 1;

    // ---- streaming loads (evict-first); do not depend on the table ----------
    const int4   lvA = __ldcs(&leaves_i4[rayA * 32 + lane]);
    const int4   lvB = __ldcs(&leaves_i4[rayB * 32 + lane]);
    const float4 tsA = __ldcs(&t_stops4[rayA * 32 + lane]);
    const float4 tsB = __ldcs(&t_stops4[rayB * 32 + lane]);

    // ---- wait for sigmoid table visibility (PDL) -----------------------------
    cudaGridDependencySynchronize();

    // ---- 8 independent gathers, back-to-back ---------------------------------
    const float oA0 = g_opacity[lvA.x & LEAF_MASK];
    const float oA1 = g_opacity[lvA.y & LEAF_MASK];
    const float oA2 = g_opacity[lvA.z & LEAF_MASK];
    const float oA3 = g_opacity[lvA.w & LEAF_MASK];
    const float oB0 = g_opacity[lvB.x & LEAF_MASK];
    const float oB1 = g_opacity[lvB.y & LEAF_MASK];
    const float oB2 = g_opacity[lvB.z & LEAF_MASK];
    const float oB3 = g_opacity[lvB.w & LEAF_MASK];

    process_ray(lane, rayA, tsA, oA0, oA1, oA2, oA3, out);
    process_ray(lane, rayB, tsB, oB0, oB1, oB2, oB3, out);
}

extern "C" void kernel_launch(void* const* d_in, const int* in_sizes, int n_in,
                              void* d_out, int out_size)
{
    const float* t_stops = (const float*)d_in[0];   // [NUM_RAYS*128] f32
    const int*   leaves  = (const int*)d_in[1];     // [NUM_RAYS*128] int32
    const float* logits  = (const float*)d_in[2];   // [NUM_LEAVES]   f32
    float* out = (float*)d_out;

    const int n4 = in_sizes[2] / 4;
    sigmoid_prepass<<<(n4 + 255) / 256, 256>>>((const float4*)logits, n4);

    // Main kernel with programmatic stream serialization (PDL): its launch and
    // streaming prologue overlap the prepass; gathers are fenced by
    // cudaGridDependencySynchronize() in-kernel.
    cudaLaunchConfig_t cfg = {};
    cfg.gridDim  = dim3(NUM_RAYS / 16, 1, 1);   // 8 warps/block, 2 rays/warp
    cfg.blockDim = dim3(256, 1, 1);
    cfg.dynamicSmemBytes = 0;
    cfg.stream = 0;
    cudaLaunchAttribute attr[1];
    attr[0].id = cudaLaunchAttributeProgrammaticStreamSerialization;
    attr[0].val.programmaticStreamSerializationAllowed = 1;
    cfg.attrs = attr;
    cfg.numAttrs = 1;

    cudaLaunchKernelEx(&cfg, volume_carver_kernel,
                       (const float4*)t_stops, (const int4*)leaves, out);
}

// round 14
// speedup vs baseline: 1.0091x; 1.0068x over previous
#include <cuda_runtime.h>
#include <cstdint>

#define NUM_RAYS   262144
#define RAY_LEN    128
#define NUM_LEAVES 1048576
#define LEAF_MASK  (NUM_LEAVES - 1)
#define MAX_DIST   1e10f
#define EPS_F      1e-10f

// Precomputed sigmoid(logits) — 4 MB device scratch.
__device__ float g_opacity[NUM_LEAVES];

// ---------------------------------------------------------------------------
// Bitwise replication of XLA:CPU's fast tanh (Eigen generic_fast_tanh_float):
// plain rn mul/add (no FMA contraction), correctly-rounded division.
// DO NOT TOUCH — 1 ulp here is ~7e-4 relative in sigmoid(-10); this is what
// makes rel_err 2.9e-4 instead of 1.7e-3.
// ---------------------------------------------------------------------------
__device__ __forceinline__ float xla_fast_tanh(float x) {
    if (fabsf(x) < 0.0004f) return x;
    float xc = fminf(fmaxf(x, -7.90531110763549805f), 7.90531110763549805f);
    float x2 = __fmul_rn(xc, xc);
    float p = -2.76076847742355e-16f;
    p = __fadd_rn(__fmul_rn(p, x2),  2.00018790482477e-13f);
    p = __fadd_rn(__fmul_rn(p, x2), -8.60467152213735e-11f);
    p = __fadd_rn(__fmul_rn(p, x2),  5.12229709037114e-08f);
    p = __fadd_rn(__fmul_rn(p, x2),  1.48572235717979e-05f);
    p = __fadd_rn(__fmul_rn(p, x2),  6.37261928875436e-04f);
    p = __fadd_rn(__fmul_rn(p, x2),  4.89352455891786e-03f);
    p = __fmul_rn(p, xc);
    float q =  1.19825839466702e-06f;
    q = __fadd_rn(__fmul_rn(q, x2),  1.18534705686654e-04f);
    q = __fadd_rn(__fmul_rn(q, x2),  2.26843463243900e-03f);
    q = __fadd_rn(__fmul_rn(q, x2),  4.89352518554385e-03f);
    return __fdiv_rn(p, q);
}

__global__ void sigmoid_prepass(const float4* __restrict__ logits4, int n4) {
    int i = blockIdx.x * blockDim.x + threadIdx.x;
    if (i < n4) {
        float4 x = logits4[i];
        float4 r;
        r.x = __fadd_rn(0.5f, __fmul_rn(0.5f, xla_fast_tanh(__fmul_rn(0.5f, x.x))));
        r.y = __fadd_rn(0.5f, __fmul_rn(0.5f, xla_fast_tanh(__fmul_rn(0.5f, x.y))));
        r.z = __fadd_rn(0.5f, __fmul_rn(0.5f, xla_fast_tanh(__fmul_rn(0.5f, x.z))));
        r.w = __fadd_rn(0.5f, __fmul_rn(0.5f, xla_fast_tanh(__fmul_rn(0.5f, x.w))));
        *reinterpret_cast<float4*>(&g_opacity[i * 4]) = r;
    }
    // PDL: table stores for this thread are done — allow dependents to launch.
    cudaTriggerProgrammaticLaunchCompletion();
}

// Near-correctly-rounded exp(-x) for x in [0, 0.0625]; expf fallback above.
// DO NOT TOUCH — load-bearing for the cancellation-amplified 1-exp(-x).
__device__ __forceinline__ float exp_neg_cr(float x) {   // x >= 0
    if (x > 0.0625f) return expf(-x);
    float hi = __fadd_rn(1.0f, -x);
    float t  = __fadd_rn(1.0f, -hi);
    float lo = __fadd_rn(t, -x);
    float c = x * x * fmaf(x, fmaf(x, fmaf(x, -8.3333333e-3f, 4.1666668e-2f),
                                   -0.16666667f), 0.5f);
    return __fadd_rn(hi, __fadd_rn(lo, c));
}

__device__ __forceinline__ void sample_terms(float o, float d,
                                             float& alpha, float& trans) {
    float x = __fmul_rn(o, d);
    float e = exp_neg_cr(x);
    alpha = __fadd_rn(1.0f, -e);
    trans = fminf(1.0f, __fadd_rn(__fadd_rn(1.0f, -alpha), EPS_F));
}

// Per-ray tail: deltas -> terms -> warp scan -> warp reduce -> out.
__device__ __forceinline__ void process_ray(int lane, int ray,
                                            const float4& ts,
                                            float o0, float o1, float o2, float o3,
                                            float* __restrict__ out)
{
    const float t_next = __shfl_down_sync(0xFFFFFFFFu, ts.x, 1);
    const float d0 = __fadd_rn(ts.y, -ts.x);
    const float d1 = __fadd_rn(ts.z, -ts.y);
    const float d2 = __fadd_rn(ts.w, -ts.z);
    const float d3 = (lane == 31) ? MAX_DIST : __fadd_rn(t_next, -ts.w);

    float a0, a1, a2, a3, tr0, tr1, tr2, tr3;
    sample_terms(o0, d0, a0, tr0);
    sample_terms(o1, d1, a1, tr1);
    sample_terms(o2, d2, a2, tr2);
    sample_terms(o3, d3, a3, tr3);

    if (lane == 0) tr0 = 1.0f;          // shifted-right leading transmittance 1

    const float p0 = tr0;
    const float p1 = p0 * tr1;
    const float p2 = p1 * tr2;
    const float p3 = p2 * tr3;

    float v = p3;
    #pragma unroll
    for (int off = 1; off < 32; off <<= 1) {
        float n = __shfl_up_sync(0xFFFFFFFFu, v, off);
        if (lane >= off) v *= n;
    }
    float pref = __shfl_up_sync(0xFFFFFFFFu, v, 1);
    if (lane == 0) pref = 1.0f;

    float s = pref * (a0 * p0 + a1 * p1 + a2 * p2 + a3 * p3);

    #pragma unroll
    for (int off = 16; off > 0; off >>= 1)
        s += __shfl_down_sync(0xFFFFFFFFu, s, off);

    if (lane == 0) out[ray] = s;
}

// Two rays per warp (empirically optimal: occ ~91%, 8-deep gather burst).
// PDL: streaming loads (independent of the opacity table) issue before the
// grid-dependency sync; gathers wait for the prepass to be visible.
__global__ __launch_bounds__(256)
void volume_carver_kernel(const float4* __restrict__ t_stops4,   // [NUM_RAYS*32]
                          const int4*   __restrict__ leaves_i4,  // [NUM_RAYS*32]
                          float*        __restrict__ out)
{
    const int lane = threadIdx.x & 31;
    const int warp = blockIdx.x * 8 + (threadIdx.x >> 5);
    const int rayA = warp * 2;
    const int rayB = rayA + 1;

    // ---- streaming loads (evict-first); do not depend on the table ----------
    const int4   lvA = __ldcs(&leaves_i4[rayA * 32 + lane]);
    const int4   lvB = __ldcs(&leaves_i4[rayB * 32 + lane]);
    const float4 tsA = __ldcs(&t_stops4[rayA * 32 + lane]);
    const float4 tsB = __ldcs(&t_stops4[rayB * 32 + lane]);

    // ---- wait for sigmoid table visibility (PDL) -----------------------------
    cudaGridDependencySynchronize();

    // ---- 8 independent gathers, back-to-back ---------------------------------
    const float oA0 = g_opacity[lvA.x & LEAF_MASK];
    const float oA1 = g_opacity[lvA.y & LEAF_MASK];
    const float oA2 = g_opacity[lvA.z & LEAF_MASK];
    const float oA3 = g_opacity[lvA.w & LEAF_MASK];
    const float oB0 = g_opacity[lvB.x & LEAF_MASK];
    const float oB1 = g_opacity[lvB.y & LEAF_MASK];
    const float oB2 = g_opacity[lvB.z & LEAF_MASK];
    const float oB3 = g_opacity[lvB.w & LEAF_MASK];

    process_ray(lane, rayA, tsA, oA0, oA1, oA2, oA3, out);
    process_ray(lane, rayB, tsB, oB0, oB1, oB2, oB3, out);
}

extern "C" void kernel_launch(void* const* d_in, const int* in_sizes, int n_in,
                              void* d_out, int out_size)
{
    const float* t_stops = (const float*)d_in[0];   // [NUM_RAYS*128] f32
    const int*   leaves  = (const int*)d_in[1];     // [NUM_RAYS*128] int32
    const float* logits  = (const float*)d_in[2];   // [NUM_LEAVES]   f32
    float* out = (float*)d_out;

    const int n4 = in_sizes[2] / 4;
    sigmoid_prepass<<<(n4 + 255) / 256, 256>>>((const float4*)logits, n4);

    // Main kernel with programmatic stream serialization (PDL): its launch and
    // streaming prologue overlap the prepass; gathers are fenced by
    // cudaGridDependencySynchronize() in-kernel.
    cudaLaunchConfig_t cfg = {};
    cfg.gridDim  = dim3(NUM_RAYS / 16, 1, 1);   // 8 warps/block, 2 rays/warp
    cfg.blockDim = dim3(256, 1, 1);
    cfg.dynamicSmemBytes = 0;
    cfg.stream = 0;
    cudaLaunchAttribute attr[1];
    attr[0].id = cudaLaunchAttributeProgrammaticStreamSerialization;
    attr[0].val.programmaticStreamSerializationAllowed = 1;
    cfg.attrs = attr;
    cfg.numAttrs = 1;

    cudaLaunchKernelEx(&cfg, volume_carver_kernel,
                       (const float4*)t_stops, (const int4*)leaves, out);
}